// round 15
// baseline (speedup 1.0000x reference)
#include <cuda_runtime.h>
#include <cuda_fp16.h>
#include <math.h>
#include <stdint.h>

#define E_    1024
#define H_    16
#define DH    64
#define B_    4
#define N_    1024
#define ROWS  (B_ * N_)      // 4096
#define FF    (4 * E_)       // 4096
#define MAXLEN 512

// ---------------- scratch (no allocs allowed) ----------------
__device__ __half g_xn[ROWS * E_];
__device__ __half g_qkv[ROWS * 3 * E_];
__device__ __half g_o[ROWS * E_];
__device__ __half g_xm[ROWS * E_];
__device__ __half g_hbuf[ROWS * FF];
__device__ __half g_wqkv[3 * E_ * E_];
__device__ __half g_wout[E_ * E_];
__device__ __half g_w1[FF * E_];
__device__ __half g_w2[E_ * FF];

__device__ __forceinline__ void mma_f16(float* c, const uint32_t* a, const uint32_t* b) {
    asm volatile(
        "mma.sync.aligned.m16n8k16.row.col.f32.f16.f16.f32 "
        "{%0,%1,%2,%3}, {%4,%5,%6,%7}, {%8,%9}, {%0,%1,%2,%3};"
        : "+f"(c[0]), "+f"(c[1]), "+f"(c[2]), "+f"(c[3])
        : "r"(a[0]), "r"(a[1]), "r"(a[2]), "r"(a[3]), "r"(b[0]), "r"(b[1]));
}

__device__ __forceinline__ void ldm_x4(uint32_t* r, uint32_t addr) {
    asm volatile("ldmatrix.sync.aligned.m8n8.x4.shared.b16 {%0,%1,%2,%3}, [%4];"
                 : "=r"(r[0]), "=r"(r[1]), "=r"(r[2]), "=r"(r[3]) : "r"(addr));
}
__device__ __forceinline__ void ldm_x4t(uint32_t* r, uint32_t addr) {
    asm volatile("ldmatrix.sync.aligned.m8n8.x4.trans.shared.b16 {%0,%1,%2,%3}, [%4];"
                 : "=r"(r[0]), "=r"(r[1]), "=r"(r[2]), "=r"(r[3]) : "r"(addr));
}

__device__ __forceinline__ void cp16(uint32_t smem_addr, const void* gptr) {
    asm volatile("cp.async.cg.shared.global [%0], [%1], 16;"
                 :: "r"(smem_addr), "l"(gptr) : "memory");
}
#define CP_COMMIT() asm volatile("cp.async.commit_group;" ::: "memory")
#define CP_WAIT2()  asm volatile("cp.async.wait_group 2;" ::: "memory")
#define CP_WAIT1()  asm volatile("cp.async.wait_group 1;" ::: "memory")

// ---------------- fused weight conversion fp32 -> fp16 ----------------
__global__ void cvt_all_kernel(const float* __restrict__ a, const float* __restrict__ b,
                               const float* __restrict__ c, const float* __restrict__ d,
                               __half* __restrict__ oa, __half* __restrict__ ob,
                               __half* __restrict__ oc, __half* __restrict__ od) {
    const int Q1 = 3 * E_ * E_ / 4;
    const int Q2 = Q1 + E_ * E_ / 4;
    const int Q3 = Q2 + FF * E_ / 4;
    int i = blockIdx.x * blockDim.x + threadIdx.x;
    const float* src; __half* dst; int off;
    if (i < Q1)      { src = a; dst = oa; off = i; }
    else if (i < Q2) { src = b; dst = ob; off = i - Q1; }
    else if (i < Q3) { src = c; dst = oc; off = i - Q2; }
    else             { src = d; dst = od; off = i - Q3; }
    float4 v = ((const float4*)src)[off];
    __half2 h0 = __floats2half2_rn(v.x, v.y);
    __half2 h1 = __floats2half2_rn(v.z, v.w);
    uint2 u = make_uint2(*(uint32_t*)&h0, *(uint32_t*)&h1);
    ((uint2*)dst)[off] = u;
}

// ---------------- LayerNorm (emits fp16) ----------------
__global__ void ln_kernel(const float* __restrict__ x, const float* __restrict__ g,
                          const float* __restrict__ bt, __half* __restrict__ out) {
    int row = blockIdx.x;
    int tid = threadIdx.x;
    const float4* xr = (const float4*)(x + (size_t)row * E_);
    float4 v = xr[tid];
    float s  = v.x + v.y + v.z + v.w;
    float s2 = v.x*v.x + v.y*v.y + v.z*v.z + v.w*v.w;
    #pragma unroll
    for (int o = 16; o; o >>= 1) {
        s  += __shfl_xor_sync(0xffffffffu, s,  o);
        s2 += __shfl_xor_sync(0xffffffffu, s2, o);
    }
    __shared__ float ws[8], ws2[8];
    int w = tid >> 5;
    if ((tid & 31) == 0) { ws[w] = s; ws2[w] = s2; }
    __syncthreads();
    if (tid < 32) {
        float a  = (tid < 8) ? ws[tid]  : 0.f;
        float a2 = (tid < 8) ? ws2[tid] : 0.f;
        #pragma unroll
        for (int o = 4; o; o >>= 1) {
            a  += __shfl_xor_sync(0xffffffffu, a,  o);
            a2 += __shfl_xor_sync(0xffffffffu, a2, o);
        }
        if (tid == 0) {
            float mu  = a / (float)E_;
            float var = a2 / (float)E_ - mu * mu;
            ws[0]  = mu;
            ws2[0] = rsqrtf(var + 1e-5f);
        }
    }
    __syncthreads();
    float mu = ws[0], rstd = ws2[0];
    float4 gv = ((const float4*)g)[tid];
    float4 bv = ((const float4*)bt)[tid];
    __half2 h0 = __floats2half2_rn((v.x - mu) * rstd * gv.x + bv.x,
                                   (v.y - mu) * rstd * gv.y + bv.y);
    __half2 h1 = __floats2half2_rn((v.z - mu) * rstd * gv.z + bv.z,
                                   (v.w - mu) * rstd * gv.w + bv.w);
    uint2 u = make_uint2(*(uint32_t*)&h0, *(uint32_t*)&h1);
    *(uint2*)(out + (size_t)row * E_ + tid * 4) = u;
}

// ---------------- fp16 mma GEMM with ldmatrix (round-11 proven) ----------------
#define BK      32
#define SSTH    40
#define STAGE_HALFS (128 * SSTH)
#define GSMEM_BYTES (4 * STAGE_HALFS * 2 * 2)

__global__ void __launch_bounds__(128, 2)
gemm_f16(const __half* __restrict__ A, const __half* __restrict__ W,
         const float* __restrict__ bias, const float* __restrict__ res,
         float* __restrict__ C, __half* __restrict__ Ch,
         int M, int Nn, int K, int relu) {
    extern __shared__ __half smemh[];
    __half* SA = smemh;
    __half* SB = smemh + 4 * STAGE_HALFS;
    uint32_t sa_u = (uint32_t)__cvta_generic_to_shared(SA);
    uint32_t sb_u = (uint32_t)__cvta_generic_to_shared(SB);

    int tid = threadIdx.x;
    int wid = tid >> 5, lane = tid & 31;
    int g = lane >> 2, t = lane & 3;
    int wm = wid >> 1, wn = wid & 1;
    int bm = blockIdx.y * 128, bn = blockIdx.x * 128;

    int lrow = tid >> 2, lc = tid & 3;
    const __half* Ag = A + (size_t)(bm + lrow) * K + lc * 8;
    const __half* Wg = W + (size_t)(bn + lrow) * K + lc * 8;
    uint32_t soff = (uint32_t)(lrow * SSTH * 2 + lc * 16);

    int arow = (lane & 7) + ((lane >> 3) & 1) * 8;
    int acol = (lane >> 4) * 8;
    int brow = (lane & 7) + (lane >> 4) * 8;
    int bcol = ((lane >> 3) & 1) * 8;

    float acc[4][8][4];
    #pragma unroll
    for (int i = 0; i < 4; i++)
        #pragma unroll
        for (int j = 0; j < 8; j++)
            #pragma unroll
            for (int v = 0; v < 4; v++) acc[i][j][v] = 0.f;

    int S = K / BK;

    auto issue = [&](int s) {
        int st = s & 3;
        int koff = s * BK;
        uint32_t sbase = (uint32_t)(st * STAGE_HALFS * 2) + soff;
        #pragma unroll
        for (int i = 0; i < 4; i++) {
            cp16(sa_u + sbase + i * 32 * SSTH * 2, Ag + (size_t)i * 32 * K + koff);
            cp16(sb_u + sbase + i * 32 * SSTH * 2, Wg + (size_t)i * 32 * K + koff);
        }
        CP_COMMIT();
    };

    issue(0); issue(1); issue(2);

    for (int s = 0; s < S; s++) {
        CP_WAIT2();
        __syncthreads();
        if (s + 3 < S) issue(s + 3);
        else CP_COMMIT();

        int st = s & 3;
        uint32_t sa_st = sa_u + (uint32_t)(st * STAGE_HALFS * 2);
        uint32_t sb_st = sb_u + (uint32_t)(st * STAGE_HALFS * 2);
        #pragma unroll
        for (int ks = 0; ks < 2; ks++) {
            int k0 = ks * 16;
            uint32_t af[4][4];
            #pragma unroll
            for (int mi = 0; mi < 4; mi++) {
                int r0 = wm * 64 + mi * 16;
                ldm_x4(af[mi], sa_st + (uint32_t)(((r0 + arow) * SSTH + k0 + acol) * 2));
            }
            uint32_t bf[8][2];
            #pragma unroll
            for (int np = 0; np < 4; np++) {
                int n0 = wn * 64 + np * 16;
                uint32_t br[4];
                ldm_x4(br, sb_st + (uint32_t)(((n0 + brow) * SSTH + k0 + bcol) * 2));
                bf[np * 2 + 0][0] = br[0]; bf[np * 2 + 0][1] = br[1];
                bf[np * 2 + 1][0] = br[2]; bf[np * 2 + 1][1] = br[3];
            }
            #pragma unroll
            for (int mi = 0; mi < 4; mi++)
                #pragma unroll
                for (int ni = 0; ni < 8; ni++)
                    mma_f16(acc[mi][ni], af[mi], bf[ni]);
        }
    }

    #pragma unroll
    for (int mi = 0; mi < 4; mi++) {
        int r0 = bm + wm * 64 + mi * 16 + g;
        #pragma unroll
        for (int half_ = 0; half_ < 2; half_++) {
            int row = r0 + half_ * 8;
            const float* rrow = res ? res + (size_t)row * Nn + bn + wn * 64 : nullptr;
            const float* brow_ = bias + bn + wn * 64;
            #pragma unroll
            for (int ni = 0; ni < 8; ni++) {
                int col = ni * 8 + 2 * t;
                float v0 = acc[mi][ni][half_ * 2 + 0] + brow_[col];
                float v1 = acc[mi][ni][half_ * 2 + 1] + brow_[col + 1];
                if (relu) { v0 = fmaxf(v0, 0.f); v1 = fmaxf(v1, 0.f); }
                if (rrow) { v0 += rrow[col]; v1 += rrow[col + 1]; }
                if (Ch) {
                    __half2 hh = __floats2half2_rn(v0, v1);
                    *(uint32_t*)(Ch + (size_t)row * Nn + bn + wn * 64 + col) =
                        *(uint32_t*)&hh;
                } else {
                    *(float2*)(C + (size_t)row * Nn + bn + wn * 64 + col) =
                        make_float2(v0, v1);
                }
            }
        }
    }
}

// ---------------- fp16 attention, register-resident P ------------------------
// smem (halfs): Kh[2][64][72] | Vh[2][64][72] | rp_s[512 floats]
#define AKST 72
#define ATILE 64
#define AK_ELTS (ATILE * AKST)
#define ASMEM_BYTES (4 * AK_ELTS * 2 + MAXLEN * 4)

__global__ void __launch_bounds__(256)
attn_kernel(const __half* __restrict__ qkv, const float* __restrict__ rel_pos,
            __half* __restrict__ o) {
    extern __shared__ __half ash[];
    __half* Kh = ash;
    __half* Vh = ash + 2 * AK_ELTS;
    float* rp_s = (float*)(ash + 4 * AK_ELTS);
    uint32_t kh_u = (uint32_t)__cvta_generic_to_shared(Kh);
    uint32_t vh_u = (uint32_t)__cvta_generic_to_shared(Vh);

    int tid = threadIdx.x;
    int wid = tid >> 5, lane = tid & 31;
    int g = lane >> 2, t = lane & 3;
    int b = blockIdx.z, h = blockIdx.y;
    int qs = blockIdx.x * 128;
    const __half* base = qkv + (size_t)b * N_ * 3 * E_;
    const float* rp = rel_pos + h * MAXLEN;

    rp_s[tid] = rp[tid];
    rp_s[tid + 256] = rp[tid + 256];

    int row0 = qs + wid * 16 + g;
    int row_lo = qs + wid * 16;
    uint32_t qf[4][4];
    {
        const __half* q0 = base + (size_t)row0 * 3 * E_ + h * DH;
        const __half* q1 = q0 + (size_t)8 * 3 * E_;
        #pragma unroll
        for (int kk = 0; kk < 4; kk++) {
            qf[kk][0] = *(const uint32_t*)(q0 + kk * 16 + 2 * t);
            qf[kk][1] = *(const uint32_t*)(q1 + kk * 16 + 2 * t);
            qf[kk][2] = *(const uint32_t*)(q0 + kk * 16 + 8 + 2 * t);
            qf[kk][3] = *(const uint32_t*)(q1 + kk * 16 + 8 + 2 * t);
        }
    }

    float oacc[8][4];
    #pragma unroll
    for (int i = 0; i < 8; i++)
        #pragma unroll
        for (int v = 0; v < 4; v++) oacc[i][v] = 0.f;
    float m_o[2] = {-INFINITY, -INFINITY};
    float lac[2] = {0.f, 0.f};

    int kt_lo = max(0, qs - (MAXLEN - 1)) >> 6;
    int kt_hi = (qs + 127) >> 6;

    int jrow = tid >> 2;
    int jc = (tid & 3) * 16;
    const __half* kgbase = base + E_ + h * DH + jc;
    const __half* vgbase = base + 2 * E_ + h * DH + jc;

    auto issueKV = [&](int kt, int buf) {
        int ks0 = kt * ATILE;
        const __half* kp = kgbase + (size_t)(ks0 + jrow) * 3 * E_;
        const __half* vp = vgbase + (size_t)(ks0 + jrow) * 3 * E_;
        uint32_t kd = kh_u + (uint32_t)((buf * AK_ELTS + jrow * AKST + jc) * 2);
        uint32_t vd = vh_u + (uint32_t)((buf * AK_ELTS + jrow * AKST + jc) * 2);
        cp16(kd, kp); cp16(kd + 16, kp + 8);
        cp16(vd, vp); cp16(vd + 16, vp + 8);
        CP_COMMIT();
    };

    issueKV(kt_lo, 0);

    // hoisted fragment-load bases (per-buf)
    int brow = (lane & 7) + (lane >> 4) * 8;
    int bcol = ((lane >> 3) & 1) * 8;
    int vkg = (lane >> 3) & 1;
    int vdg = (lane >> 4) & 1;
    int vrr = lane & 7;
    uint32_t kbase0 = kh_u + (uint32_t)((brow * AKST + bcol) * 2);
    uint32_t vbase0 = vh_u + (uint32_t)(((vkg * 8 + vrr) * AKST + vdg * 8) * 2);

    for (int kt = kt_lo; kt <= kt_hi; kt++) {
        int buf = (kt - kt_lo) & 1;
        __syncthreads();
        if (kt + 1 <= kt_hi) issueKV(kt + 1, buf ^ 1);
        else CP_COMMIT();
        CP_WAIT1();
        __syncthreads();

        int ks0 = kt * ATILE;
        if (ks0 > row_lo + 15 || ks0 + (ATILE - 1) < row_lo - (MAXLEN - 1))
            continue;

        uint32_t kb = kbase0 + (uint32_t)(buf * AK_ELTS * 2);
        uint32_t vbb = vbase0 + (uint32_t)(buf * AK_ELTS * 2);

        // ---- S = Q K^T (16 x 64 per warp) ----
        float sacc[8][4];
        #pragma unroll
        for (int ni = 0; ni < 8; ni++)
            #pragma unroll
            for (int v = 0; v < 4; v++) sacc[ni][v] = 0.f;
        #pragma unroll
        for (int kk = 0; kk < 4; kk++) {
            uint32_t bf[8][2];
            #pragma unroll
            for (int np = 0; np < 4; np++) {
                uint32_t br[4];
                ldm_x4(br, kb + (uint32_t)((np * 16 * AKST + kk * 16) * 2));
                bf[np * 2 + 0][0] = br[0]; bf[np * 2 + 0][1] = br[1];
                bf[np * 2 + 1][0] = br[2]; bf[np * 2 + 1][1] = br[3];
            }
            #pragma unroll
            for (int ni = 0; ni < 8; ni++)
                mma_f16(sacc[ni], qf[kk], bf[ni]);
        }

        // ---- scale + bias (+mask on boundary) + online softmax ----
        int drel = row0 - ks0 - 2 * t;
        float m_t[2] = {-INFINITY, -INFINITY};
        bool interior = (ks0 <= row_lo - 63) && (ks0 >= row_lo - (MAXLEN - 16));
        if (interior) {
            #pragma unroll
            for (int ni = 0; ni < 8; ni++) {
                #pragma unroll
                for (int v = 0; v < 4; v++) {
                    int r = v >> 1;
                    float val = sacc[ni][v] * 0.125f
                              + rp_s[drel + r * 8 - ni * 8 - (v & 1)];
                    sacc[ni][v] = val;
                    m_t[r] = fmaxf(m_t[r], val);
                }
            }
        } else {
            #pragma unroll
            for (int ni = 0; ni < 8; ni++) {
                #pragma unroll
                for (int v = 0; v < 4; v++) {
                    int r = v >> 1;
                    int rel = drel + r * 8 - ni * 8 - (v & 1);
                    float val;
                    if (rel >= 0 && rel < MAXLEN)
                        val = sacc[ni][v] * 0.125f + rp_s[rel];
                    else
                        val = -INFINITY;
                    sacc[ni][v] = val;
                    m_t[r] = fmaxf(m_t[r], val);
                }
            }
        }
        #pragma unroll
        for (int r = 0; r < 2; r++) {
            m_t[r] = fmaxf(m_t[r], __shfl_xor_sync(0xffffffffu, m_t[r], 1));
            m_t[r] = fmaxf(m_t[r], __shfl_xor_sync(0xffffffffu, m_t[r], 2));
        }
        float fac[2], m_n[2];
        #pragma unroll
        for (int r = 0; r < 2; r++) {
            m_n[r] = fmaxf(m_o[r], m_t[r]);
            fac[r] = (m_n[r] == -INFINITY) ? 1.f : __expf(m_o[r] - m_n[r]);
            if (m_o[r] == -INFINITY) fac[r] = 0.f;
            if (m_n[r] == -INFINITY) fac[r] = 1.f;
        }
        // p = exp(s - m), kept in registers; pack into fp16 A-fragments directly
        float psum[2] = {0.f, 0.f};
        uint32_t pf[4][4];     // [k-chunk kk][a-frag]
        #pragma unroll
        for (int ni = 0; ni < 8; ni++) {
            float p0 = (m_n[0] == -INFINITY) ? 0.f : __expf(sacc[ni][0] - m_n[0]);
            float p1 = (m_n[0] == -INFINITY) ? 0.f : __expf(sacc[ni][1] - m_n[0]);
            float p2 = (m_n[1] == -INFINITY) ? 0.f : __expf(sacc[ni][2] - m_n[1]);
            float p3 = (m_n[1] == -INFINITY) ? 0.f : __expf(sacc[ni][3] - m_n[1]);
            psum[0] += p0 + p1;
            psum[1] += p2 + p3;
            __half2 h01 = __floats2half2_rn(p0, p1);
            __half2 h23 = __floats2half2_rn(p2, p3);
            int kk = ni >> 1, sub = ni & 1;     // S cols ni*8.. -> chunk kk, half sub
            pf[kk][sub * 2 + 0] = *(uint32_t*)&h01;   // rows g
            pf[kk][sub * 2 + 1] = *(uint32_t*)&h23;   // rows g+8
        }
        // reorder: a-frag = {row g k-lo, row g+8 k-lo, row g k-hi, row g+8 k-hi}
        // built above as pf[kk] = {g lo, g+8 lo, g hi, g+8 hi} — matches a0..a3
        #pragma unroll
        for (int r = 0; r < 2; r++) {
            psum[r] += __shfl_xor_sync(0xffffffffu, psum[r], 1);
            psum[r] += __shfl_xor_sync(0xffffffffu, psum[r], 2);
            lac[r] = lac[r] * fac[r] + psum[r];
            m_o[r] = m_n[r];
        }
        #pragma unroll
        for (int i = 0; i < 8; i++) {
            oacc[i][0] *= fac[0]; oacc[i][1] *= fac[0];
            oacc[i][2] *= fac[1]; oacc[i][3] *= fac[1];
        }

        // ---- O += P V (k = 64), P from registers ----
        #pragma unroll
        for (int kk = 0; kk < 4; kk++) {
            #pragma unroll
            for (int np = 0; np < 4; np++) {
                uint32_t br[4];
                ldm_x4t(br, vbb + (uint32_t)((kk * 16 * AKST + np * 16) * 2));
                uint32_t b0[2] = {br[0], br[1]};
                uint32_t b1[2] = {br[2], br[3]};
                mma_f16(oacc[np * 2 + 0], pf[kk], b0);
                mma_f16(oacc[np * 2 + 1], pf[kk], b1);
            }
        }
    }

    float inv0 = 1.f / lac[0];
    float inv1 = 1.f / lac[1];
    __half* op0 = o + ((size_t)(b * N_) + row0) * E_ + h * DH;
    __half* op1 = op0 + (size_t)8 * E_;
    #pragma unroll
    for (int ni = 0; ni < 8; ni++) {
        int col = ni * 8 + 2 * t;
        __half2 h0 = __floats2half2_rn(oacc[ni][0] * inv0, oacc[ni][1] * inv0);
        __half2 h1 = __floats2half2_rn(oacc[ni][2] * inv1, oacc[ni][3] * inv1);
        *(uint32_t*)(op0 + col) = *(uint32_t*)&h0;
        *(uint32_t*)(op1 + col) = *(uint32_t*)&h1;
    }
}

// ---------------- driver ----------------
extern "C" void kernel_launch(void* const* d_in, const int* in_sizes, int n_in,
                              void* d_out, int out_size) {
    const float* x         = (const float*)d_in[0];
    const float* rel_pos   = (const float*)d_in[1];
    const float* in_proj_w = (const float*)d_in[2];
    const float* in_proj_b = (const float*)d_in[3];
    const float* out_w     = (const float*)d_in[4];
    const float* out_b     = (const float*)d_in[5];
    const float* w1        = (const float*)d_in[6];
    const float* b1        = (const float*)d_in[7];
    const float* w2        = (const float*)d_in[8];
    const float* b2        = (const float*)d_in[9];
    const float* ln1_g     = (const float*)d_in[10];
    const float* ln1_b     = (const float*)d_in[11];
    const float* ln2_g     = (const float*)d_in[12];
    const float* ln2_b     = (const float*)d_in[13];
    float* out = (float*)d_out;

    __half *xn, *qkv, *o, *xm, *hbuf, *wqkv, *wout, *w1h, *w2h;
    cudaGetSymbolAddress((void**)&xn,   g_xn);
    cudaGetSymbolAddress((void**)&qkv,  g_qkv);
    cudaGetSymbolAddress((void**)&o,    g_o);
    cudaGetSymbolAddress((void**)&xm,   g_xm);
    cudaGetSymbolAddress((void**)&hbuf, g_hbuf);
    cudaGetSymbolAddress((void**)&wqkv, g_wqkv);
    cudaGetSymbolAddress((void**)&wout, g_wout);
    cudaGetSymbolAddress((void**)&w1h,  g_w1);
    cudaGetSymbolAddress((void**)&w2h,  g_w2);

    cudaFuncSetAttribute(gemm_f16, cudaFuncAttributeMaxDynamicSharedMemorySize,
                         GSMEM_BYTES);
    cudaFuncSetAttribute(attn_kernel, cudaFuncAttributeMaxDynamicSharedMemorySize,
                         ASMEM_BYTES);

    cvt_all_kernel<<<12 * E_ * E_ / 1024, 256>>>(in_proj_w, out_w, w1, w2,
                                                 wqkv, wout, w1h, w2h);

    ln_kernel<<<ROWS, 256>>>(x, ln1_g, ln1_b, xn);
    gemm_f16<<<dim3(3 * E_ / 128, ROWS / 128), 128, GSMEM_BYTES>>>(
        xn, wqkv, in_proj_b, nullptr, nullptr, qkv, ROWS, 3 * E_, E_, 0);
    attn_kernel<<<dim3(N_ / 128, H_, B_), 256, ASMEM_BYTES>>>(qkv, rel_pos, o);
    gemm_f16<<<dim3(E_ / 128, ROWS / 128), 128, GSMEM_BYTES>>>(
        o, wout, out_b, x, out, nullptr, ROWS, E_, E_, 0);
    ln_kernel<<<ROWS, 256>>>(out, ln2_g, ln2_b, xm);
    gemm_f16<<<dim3(FF / 128, ROWS / 128), 128, GSMEM_BYTES>>>(
        xm, w1h, b1, nullptr, nullptr, hbuf, ROWS, FF, E_, 1);
    gemm_f16<<<dim3(E_ / 128, ROWS / 128), 128, GSMEM_BYTES>>>(
        hbuf, w2h, b2, out, out, nullptr, ROWS, E_, FF, 0);
}

// round 16
// speedup vs baseline: 1.0169x; 1.0169x over previous
#include <cuda_runtime.h>
#include <cuda_fp16.h>
#include <math.h>
#include <stdint.h>

#define E_    1024
#define H_    16
#define DH    64
#define B_    4
#define N_    1024
#define ROWS  (B_ * N_)      // 4096
#define FF    (4 * E_)       // 4096
#define MAXLEN 512

// ---------------- scratch (no allocs allowed) ----------------
__device__ __half g_xn[ROWS * E_];
__device__ __half g_qkv[ROWS * 3 * E_];
__device__ __half g_o[ROWS * E_];
__device__ __half g_xm[ROWS * E_];
__device__ __half g_hbuf[ROWS * FF];
__device__ __half g_wqkv[3 * E_ * E_];
__device__ __half g_wout[E_ * E_];
__device__ __half g_w1[FF * E_];
__device__ __half g_w2[E_ * FF];

__device__ __forceinline__ void mma_f16(float* c, const uint32_t* a, const uint32_t* b) {
    asm volatile(
        "mma.sync.aligned.m16n8k16.row.col.f32.f16.f16.f32 "
        "{%0,%1,%2,%3}, {%4,%5,%6,%7}, {%8,%9}, {%0,%1,%2,%3};"
        : "+f"(c[0]), "+f"(c[1]), "+f"(c[2]), "+f"(c[3])
        : "r"(a[0]), "r"(a[1]), "r"(a[2]), "r"(a[3]), "r"(b[0]), "r"(b[1]));
}

__device__ __forceinline__ void ldm_x4(uint32_t* r, uint32_t addr) {
    asm volatile("ldmatrix.sync.aligned.m8n8.x4.shared.b16 {%0,%1,%2,%3}, [%4];"
                 : "=r"(r[0]), "=r"(r[1]), "=r"(r[2]), "=r"(r[3]) : "r"(addr));
}
__device__ __forceinline__ void ldm_x4t(uint32_t* r, uint32_t addr) {
    asm volatile("ldmatrix.sync.aligned.m8n8.x4.trans.shared.b16 {%0,%1,%2,%3}, [%4];"
                 : "=r"(r[0]), "=r"(r[1]), "=r"(r[2]), "=r"(r[3]) : "r"(addr));
}

__device__ __forceinline__ void cp16(uint32_t smem_addr, const void* gptr) {
    asm volatile("cp.async.cg.shared.global [%0], [%1], 16;"
                 :: "r"(smem_addr), "l"(gptr) : "memory");
}
#define CP_COMMIT() asm volatile("cp.async.commit_group;" ::: "memory")
#define CP_WAIT2()  asm volatile("cp.async.wait_group 2;" ::: "memory")
#define CP_WAIT1()  asm volatile("cp.async.wait_group 1;" ::: "memory")

// ---------------- LN1 + fused weight conversion ----------------
// blocks [0, ROWS): layernorm rows; blocks [ROWS, ROWS+12288): weight cvt
__global__ void ln_cvt_kernel(const float* __restrict__ x, const float* __restrict__ g,
                              const float* __restrict__ bt, __half* __restrict__ out,
                              const float* __restrict__ wa, const float* __restrict__ wb,
                              const float* __restrict__ wc, const float* __restrict__ wd,
                              __half* __restrict__ oa, __half* __restrict__ ob,
                              __half* __restrict__ oc, __half* __restrict__ od) {
    int tid = threadIdx.x;
    if (blockIdx.x >= ROWS) {
        // ---- weight conversion path ----
        const int Q1 = 3 * E_ * E_ / 4;
        const int Q2 = Q1 + E_ * E_ / 4;
        const int Q3 = Q2 + FF * E_ / 4;
        int i = (blockIdx.x - ROWS) * blockDim.x + tid;
        const float* src; __half* dst; int off;
        if (i < Q1)      { src = wa; dst = oa; off = i; }
        else if (i < Q2) { src = wb; dst = ob; off = i - Q1; }
        else if (i < Q3) { src = wc; dst = oc; off = i - Q2; }
        else             { src = wd; dst = od; off = i - Q3; }
        float4 v = ((const float4*)src)[off];
        __half2 h0 = __floats2half2_rn(v.x, v.y);
        __half2 h1 = __floats2half2_rn(v.z, v.w);
        uint2 u = make_uint2(*(uint32_t*)&h0, *(uint32_t*)&h1);
        ((uint2*)dst)[off] = u;
        return;
    }
    // ---- layernorm path ----
    int row = blockIdx.x;
    const float4* xr = (const float4*)(x + (size_t)row * E_);
    float4 v = xr[tid];
    float s  = v.x + v.y + v.z + v.w;
    float s2 = v.x*v.x + v.y*v.y + v.z*v.z + v.w*v.w;
    #pragma unroll
    for (int o = 16; o; o >>= 1) {
        s  += __shfl_xor_sync(0xffffffffu, s,  o);
        s2 += __shfl_xor_sync(0xffffffffu, s2, o);
    }
    __shared__ float ws[8], ws2[8];
    int w = tid >> 5;
    if ((tid & 31) == 0) { ws[w] = s; ws2[w] = s2; }
    __syncthreads();
    if (tid < 32) {
        float a  = (tid < 8) ? ws[tid]  : 0.f;
        float a2 = (tid < 8) ? ws2[tid] : 0.f;
        #pragma unroll
        for (int o = 4; o; o >>= 1) {
            a  += __shfl_xor_sync(0xffffffffu, a,  o);
            a2 += __shfl_xor_sync(0xffffffffu, a2, o);
        }
        if (tid == 0) {
            float mu  = a / (float)E_;
            float var = a2 / (float)E_ - mu * mu;
            ws[0]  = mu;
            ws2[0] = rsqrtf(var + 1e-5f);
        }
    }
    __syncthreads();
    float mu = ws[0], rstd = ws2[0];
    float4 gv = ((const float4*)g)[tid];
    float4 bv = ((const float4*)bt)[tid];
    __half2 h0 = __floats2half2_rn((v.x - mu) * rstd * gv.x + bv.x,
                                   (v.y - mu) * rstd * gv.y + bv.y);
    __half2 h1 = __floats2half2_rn((v.z - mu) * rstd * gv.z + bv.z,
                                   (v.w - mu) * rstd * gv.w + bv.w);
    uint2 u = make_uint2(*(uint32_t*)&h0, *(uint32_t*)&h1);
    *(uint2*)(out + (size_t)row * E_ + tid * 4) = u;
}

// ---------------- plain LayerNorm (emits fp16) ----------------
__global__ void ln_kernel(const float* __restrict__ x, const float* __restrict__ g,
                          const float* __restrict__ bt, __half* __restrict__ out) {
    int row = blockIdx.x;
    int tid = threadIdx.x;
    const float4* xr = (const float4*)(x + (size_t)row * E_);
    float4 v = xr[tid];
    float s  = v.x + v.y + v.z + v.w;
    float s2 = v.x*v.x + v.y*v.y + v.z*v.z + v.w*v.w;
    #pragma unroll
    for (int o = 16; o; o >>= 1) {
        s  += __shfl_xor_sync(0xffffffffu, s,  o);
        s2 += __shfl_xor_sync(0xffffffffu, s2, o);
    }
    __shared__ float ws[8], ws2[8];
    int w = tid >> 5;
    if ((tid & 31) == 0) { ws[w] = s; ws2[w] = s2; }
    __syncthreads();
    if (tid < 32) {
        float a  = (tid < 8) ? ws[tid]  : 0.f;
        float a2 = (tid < 8) ? ws2[tid] : 0.f;
        #pragma unroll
        for (int o = 4; o; o >>= 1) {
            a  += __shfl_xor_sync(0xffffffffu, a,  o);
            a2 += __shfl_xor_sync(0xffffffffu, a2, o);
        }
        if (tid == 0) {
            float mu  = a / (float)E_;
            float var = a2 / (float)E_ - mu * mu;
            ws[0]  = mu;
            ws2[0] = rsqrtf(var + 1e-5f);
        }
    }
    __syncthreads();
    float mu = ws[0], rstd = ws2[0];
    float4 gv = ((const float4*)g)[tid];
    float4 bv = ((const float4*)bt)[tid];
    __half2 h0 = __floats2half2_rn((v.x - mu) * rstd * gv.x + bv.x,
                                   (v.y - mu) * rstd * gv.y + bv.y);
    __half2 h1 = __floats2half2_rn((v.z - mu) * rstd * gv.z + bv.z,
                                   (v.w - mu) * rstd * gv.w + bv.w);
    uint2 u = make_uint2(*(uint32_t*)&h0, *(uint32_t*)&h1);
    *(uint2*)(out + (size_t)row * E_ + tid * 4) = u;
}

// ---------------- fp16 mma GEMM with ldmatrix (round-11 proven) ----------------
#define BK      32
#define SSTH    40
#define STAGE_HALFS (128 * SSTH)
#define GSMEM_BYTES (4 * STAGE_HALFS * 2 * 2)

__global__ void __launch_bounds__(128, 2)
gemm_f16(const __half* __restrict__ A, const __half* __restrict__ W,
         const float* __restrict__ bias, const float* __restrict__ res,
         float* __restrict__ C, __half* __restrict__ Ch,
         int M, int Nn, int K, int relu) {
    extern __shared__ __half smemh[];
    __half* SA = smemh;
    __half* SB = smemh + 4 * STAGE_HALFS;
    uint32_t sa_u = (uint32_t)__cvta_generic_to_shared(SA);
    uint32_t sb_u = (uint32_t)__cvta_generic_to_shared(SB);

    int tid = threadIdx.x;
    int wid = tid >> 5, lane = tid & 31;
    int g = lane >> 2, t = lane & 3;
    int wm = wid >> 1, wn = wid & 1;
    int bm = blockIdx.y * 128, bn = blockIdx.x * 128;

    int lrow = tid >> 2, lc = tid & 3;
    const __half* Ag = A + (size_t)(bm + lrow) * K + lc * 8;
    const __half* Wg = W + (size_t)(bn + lrow) * K + lc * 8;
    uint32_t soff = (uint32_t)(lrow * SSTH * 2 + lc * 16);

    int arow = (lane & 7) + ((lane >> 3) & 1) * 8;
    int acol = (lane >> 4) * 8;
    int brow = (lane & 7) + (lane >> 4) * 8;
    int bcol = ((lane >> 3) & 1) * 8;

    float acc[4][8][4];
    #pragma unroll
    for (int i = 0; i < 4; i++)
        #pragma unroll
        for (int j = 0; j < 8; j++)
            #pragma unroll
            for (int v = 0; v < 4; v++) acc[i][j][v] = 0.f;

    int S = K / BK;

    auto issue = [&](int s) {
        int st = s & 3;
        int koff = s * BK;
        uint32_t sbase = (uint32_t)(st * STAGE_HALFS * 2) + soff;
        #pragma unroll
        for (int i = 0; i < 4; i++) {
            cp16(sa_u + sbase + i * 32 * SSTH * 2, Ag + (size_t)i * 32 * K + koff);
            cp16(sb_u + sbase + i * 32 * SSTH * 2, Wg + (size_t)i * 32 * K + koff);
        }
        CP_COMMIT();
    };

    issue(0); issue(1); issue(2);

    for (int s = 0; s < S; s++) {
        CP_WAIT2();
        __syncthreads();
        if (s + 3 < S) issue(s + 3);
        else CP_COMMIT();

        int st = s & 3;
        uint32_t sa_st = sa_u + (uint32_t)(st * STAGE_HALFS * 2);
        uint32_t sb_st = sb_u + (uint32_t)(st * STAGE_HALFS * 2);
        #pragma unroll
        for (int ks = 0; ks < 2; ks++) {
            int k0 = ks * 16;
            uint32_t af[4][4];
            #pragma unroll
            for (int mi = 0; mi < 4; mi++) {
                int r0 = wm * 64 + mi * 16;
                ldm_x4(af[mi], sa_st + (uint32_t)(((r0 + arow) * SSTH + k0 + acol) * 2));
            }
            uint32_t bf[8][2];
            #pragma unroll
            for (int np = 0; np < 4; np++) {
                int n0 = wn * 64 + np * 16;
                uint32_t br[4];
                ldm_x4(br, sb_st + (uint32_t)(((n0 + brow) * SSTH + k0 + bcol) * 2));
                bf[np * 2 + 0][0] = br[0]; bf[np * 2 + 0][1] = br[1];
                bf[np * 2 + 1][0] = br[2]; bf[np * 2 + 1][1] = br[3];
            }
            #pragma unroll
            for (int mi = 0; mi < 4; mi++)
                #pragma unroll
                for (int ni = 0; ni < 8; ni++)
                    mma_f16(acc[mi][ni], af[mi], bf[ni]);
        }
    }

    #pragma unroll
    for (int mi = 0; mi < 4; mi++) {
        int r0 = bm + wm * 64 + mi * 16 + g;
        #pragma unroll
        for (int half_ = 0; half_ < 2; half_++) {
            int row = r0 + half_ * 8;
            const float* rrow = res ? res + (size_t)row * Nn + bn + wn * 64 : nullptr;
            const float* brow_ = bias + bn + wn * 64;
            #pragma unroll
            for (int ni = 0; ni < 8; ni++) {
                int col = ni * 8 + 2 * t;
                float v0 = acc[mi][ni][half_ * 2 + 0] + brow_[col];
                float v1 = acc[mi][ni][half_ * 2 + 1] + brow_[col + 1];
                if (relu) { v0 = fmaxf(v0, 0.f); v1 = fmaxf(v1, 0.f); }
                if (rrow) { v0 += rrow[col]; v1 += rrow[col + 1]; }
                if (Ch) {
                    __half2 hh = __floats2half2_rn(v0, v1);
                    *(uint32_t*)(Ch + (size_t)row * Nn + bn + wn * 64 + col) =
                        *(uint32_t*)&hh;
                } else {
                    *(float2*)(C + (size_t)row * Nn + bn + wn * 64 + col) =
                        make_float2(v0, v1);
                }
            }
        }
    }
}

// ---------------- fp16 attention, register-resident P (round-15) -------------
#define AKST 72
#define ATILE 64
#define AK_ELTS (ATILE * AKST)
#define ASMEM_BYTES (4 * AK_ELTS * 2 + MAXLEN * 4)

__global__ void __launch_bounds__(256)
attn_kernel(const __half* __restrict__ qkv, const float* __restrict__ rel_pos,
            __half* __restrict__ o) {
    extern __shared__ __half ash[];
    __half* Kh = ash;
    __half* Vh = ash + 2 * AK_ELTS;
    float* rp_s = (float*)(ash + 4 * AK_ELTS);
    uint32_t kh_u = (uint32_t)__cvta_generic_to_shared(Kh);
    uint32_t vh_u = (uint32_t)__cvta_generic_to_shared(Vh);

    int tid = threadIdx.x;
    int wid = tid >> 5, lane = tid & 31;
    int g = lane >> 2, t = lane & 3;
    int b = blockIdx.z, h = blockIdx.y;
    int qs = blockIdx.x * 128;
    const __half* base = qkv + (size_t)b * N_ * 3 * E_;
    const float* rp = rel_pos + h * MAXLEN;

    rp_s[tid] = rp[tid];
    rp_s[tid + 256] = rp[tid + 256];

    int row0 = qs + wid * 16 + g;
    int row_lo = qs + wid * 16;
    uint32_t qf[4][4];
    {
        const __half* q0 = base + (size_t)row0 * 3 * E_ + h * DH;
        const __half* q1 = q0 + (size_t)8 * 3 * E_;
        #pragma unroll
        for (int kk = 0; kk < 4; kk++) {
            qf[kk][0] = *(const uint32_t*)(q0 + kk * 16 + 2 * t);
            qf[kk][1] = *(const uint32_t*)(q1 + kk * 16 + 2 * t);
            qf[kk][2] = *(const uint32_t*)(q0 + kk * 16 + 8 + 2 * t);
            qf[kk][3] = *(const uint32_t*)(q1 + kk * 16 + 8 + 2 * t);
        }
    }

    float oacc[8][4];
    #pragma unroll
    for (int i = 0; i < 8; i++)
        #pragma unroll
        for (int v = 0; v < 4; v++) oacc[i][v] = 0.f;
    float m_o[2] = {-INFINITY, -INFINITY};
    float lac[2] = {0.f, 0.f};

    int kt_lo = max(0, qs - (MAXLEN - 1)) >> 6;
    int kt_hi = (qs + 127) >> 6;

    int jrow = tid >> 2;
    int jc = (tid & 3) * 16;
    const __half* kgbase = base + E_ + h * DH + jc;
    const __half* vgbase = base + 2 * E_ + h * DH + jc;

    auto issueKV = [&](int kt, int buf) {
        int ks0 = kt * ATILE;
        const __half* kp = kgbase + (size_t)(ks0 + jrow) * 3 * E_;
        const __half* vp = vgbase + (size_t)(ks0 + jrow) * 3 * E_;
        uint32_t kd = kh_u + (uint32_t)((buf * AK_ELTS + jrow * AKST + jc) * 2);
        uint32_t vd = vh_u + (uint32_t)((buf * AK_ELTS + jrow * AKST + jc) * 2);
        cp16(kd, kp); cp16(kd + 16, kp + 8);
        cp16(vd, vp); cp16(vd + 16, vp + 8);
        CP_COMMIT();
    };

    issueKV(kt_lo, 0);

    int brow = (lane & 7) + (lane >> 4) * 8;
    int bcol = ((lane >> 3) & 1) * 8;
    int vkg = (lane >> 3) & 1;
    int vdg = (lane >> 4) & 1;
    int vrr = lane & 7;
    uint32_t kbase0 = kh_u + (uint32_t)((brow * AKST + bcol) * 2);
    uint32_t vbase0 = vh_u + (uint32_t)(((vkg * 8 + vrr) * AKST + vdg * 8) * 2);

    for (int kt = kt_lo; kt <= kt_hi; kt++) {
        int buf = (kt - kt_lo) & 1;
        __syncthreads();
        if (kt + 1 <= kt_hi) issueKV(kt + 1, buf ^ 1);
        else CP_COMMIT();
        CP_WAIT1();
        __syncthreads();

        int ks0 = kt * ATILE;
        if (ks0 > row_lo + 15 || ks0 + (ATILE - 1) < row_lo - (MAXLEN - 1))
            continue;

        uint32_t kb = kbase0 + (uint32_t)(buf * AK_ELTS * 2);
        uint32_t vbb = vbase0 + (uint32_t)(buf * AK_ELTS * 2);

        float sacc[8][4];
        #pragma unroll
        for (int ni = 0; ni < 8; ni++)
            #pragma unroll
            for (int v = 0; v < 4; v++) sacc[ni][v] = 0.f;
        #pragma unroll
        for (int kk = 0; kk < 4; kk++) {
            uint32_t bf[8][2];
            #pragma unroll
            for (int np = 0; np < 4; np++) {
                uint32_t br[4];
                ldm_x4(br, kb + (uint32_t)((np * 16 * AKST + kk * 16) * 2));
                bf[np * 2 + 0][0] = br[0]; bf[np * 2 + 0][1] = br[1];
                bf[np * 2 + 1][0] = br[2]; bf[np * 2 + 1][1] = br[3];
            }
            #pragma unroll
            for (int ni = 0; ni < 8; ni++)
                mma_f16(sacc[ni], qf[kk], bf[ni]);
        }

        int drel = row0 - ks0 - 2 * t;
        float m_t[2] = {-INFINITY, -INFINITY};
        bool interior = (ks0 <= row_lo - 63) && (ks0 >= row_lo - (MAXLEN - 16));
        if (interior) {
            #pragma unroll
            for (int ni = 0; ni < 8; ni++) {
                #pragma unroll
                for (int v = 0; v < 4; v++) {
                    int r = v >> 1;
                    float val = sacc[ni][v] * 0.125f
                              + rp_s[drel + r * 8 - ni * 8 - (v & 1)];
                    sacc[ni][v] = val;
                    m_t[r] = fmaxf(m_t[r], val);
                }
            }
        } else {
            #pragma unroll
            for (int ni = 0; ni < 8; ni++) {
                #pragma unroll
                for (int v = 0; v < 4; v++) {
                    int r = v >> 1;
                    int rel = drel + r * 8 - ni * 8 - (v & 1);
                    float val;
                    if (rel >= 0 && rel < MAXLEN)
                        val = sacc[ni][v] * 0.125f + rp_s[rel];
                    else
                        val = -INFINITY;
                    sacc[ni][v] = val;
                    m_t[r] = fmaxf(m_t[r], val);
                }
            }
        }
        #pragma unroll
        for (int r = 0; r < 2; r++) {
            m_t[r] = fmaxf(m_t[r], __shfl_xor_sync(0xffffffffu, m_t[r], 1));
            m_t[r] = fmaxf(m_t[r], __shfl_xor_sync(0xffffffffu, m_t[r], 2));
        }
        float fac[2], m_n[2];
        #pragma unroll
        for (int r = 0; r < 2; r++) {
            m_n[r] = fmaxf(m_o[r], m_t[r]);
            fac[r] = (m_n[r] == -INFINITY) ? 1.f : __expf(m_o[r] - m_n[r]);
            if (m_o[r] == -INFINITY) fac[r] = 0.f;
            if (m_n[r] == -INFINITY) fac[r] = 1.f;
        }
        float psum[2] = {0.f, 0.f};
        uint32_t pf[4][4];
        #pragma unroll
        for (int ni = 0; ni < 8; ni++) {
            float p0 = (m_n[0] == -INFINITY) ? 0.f : __expf(sacc[ni][0] - m_n[0]);
            float p1 = (m_n[0] == -INFINITY) ? 0.f : __expf(sacc[ni][1] - m_n[0]);
            float p2 = (m_n[1] == -INFINITY) ? 0.f : __expf(sacc[ni][2] - m_n[1]);
            float p3 = (m_n[1] == -INFINITY) ? 0.f : __expf(sacc[ni][3] - m_n[1]);
            psum[0] += p0 + p1;
            psum[1] += p2 + p3;
            __half2 h01 = __floats2half2_rn(p0, p1);
            __half2 h23 = __floats2half2_rn(p2, p3);
            int kk = ni >> 1, sub = ni & 1;
            pf[kk][sub * 2 + 0] = *(uint32_t*)&h01;
            pf[kk][sub * 2 + 1] = *(uint32_t*)&h23;
        }
        #pragma unroll
        for (int r = 0; r < 2; r++) {
            psum[r] += __shfl_xor_sync(0xffffffffu, psum[r], 1);
            psum[r] += __shfl_xor_sync(0xffffffffu, psum[r], 2);
            lac[r] = lac[r] * fac[r] + psum[r];
            m_o[r] = m_n[r];
        }
        #pragma unroll
        for (int i = 0; i < 8; i++) {
            oacc[i][0] *= fac[0]; oacc[i][1] *= fac[0];
            oacc[i][2] *= fac[1]; oacc[i][3] *= fac[1];
        }

        #pragma unroll
        for (int kk = 0; kk < 4; kk++) {
            #pragma unroll
            for (int np = 0; np < 4; np++) {
                uint32_t br[4];
                ldm_x4t(br, vbb + (uint32_t)((kk * 16 * AKST + np * 16) * 2));
                uint32_t b0[2] = {br[0], br[1]};
                uint32_t b1[2] = {br[2], br[3]};
                mma_f16(oacc[np * 2 + 0], pf[kk], b0);
                mma_f16(oacc[np * 2 + 1], pf[kk], b1);
            }
        }
    }

    float inv0 = 1.f / lac[0];
    float inv1 = 1.f / lac[1];
    __half* op0 = o + ((size_t)(b * N_) + row0) * E_ + h * DH;
    __half* op1 = op0 + (size_t)8 * E_;
    #pragma unroll
    for (int ni = 0; ni < 8; ni++) {
        int col = ni * 8 + 2 * t;
        __half2 h0 = __floats2half2_rn(oacc[ni][0] * inv0, oacc[ni][1] * inv0);
        __half2 h1 = __floats2half2_rn(oacc[ni][2] * inv1, oacc[ni][3] * inv1);
        *(uint32_t*)(op0 + col) = *(uint32_t*)&h0;
        *(uint32_t*)(op1 + col) = *(uint32_t*)&h1;
    }
}

// ---------------- driver ----------------
extern "C" void kernel_launch(void* const* d_in, const int* in_sizes, int n_in,
                              void* d_out, int out_size) {
    const float* x         = (const float*)d_in[0];
    const float* rel_pos   = (const float*)d_in[1];
    const float* in_proj_w = (const float*)d_in[2];
    const float* in_proj_b = (const float*)d_in[3];
    const float* out_w     = (const float*)d_in[4];
    const float* out_b     = (const float*)d_in[5];
    const float* w1        = (const float*)d_in[6];
    const float* b1        = (const float*)d_in[7];
    const float* w2        = (const float*)d_in[8];
    const float* b2        = (const float*)d_in[9];
    const float* ln1_g     = (const float*)d_in[10];
    const float* ln1_b     = (const float*)d_in[11];
    const float* ln2_g     = (const float*)d_in[12];
    const float* ln2_b     = (const float*)d_in[13];
    float* out = (float*)d_out;

    __half *xn, *qkv, *o, *xm, *hbuf, *wqkv, *wout, *w1h, *w2h;
    cudaGetSymbolAddress((void**)&xn,   g_xn);
    cudaGetSymbolAddress((void**)&qkv,  g_qkv);
    cudaGetSymbolAddress((void**)&o,    g_o);
    cudaGetSymbolAddress((void**)&xm,   g_xm);
    cudaGetSymbolAddress((void**)&hbuf, g_hbuf);
    cudaGetSymbolAddress((void**)&wqkv, g_wqkv);
    cudaGetSymbolAddress((void**)&wout, g_wout);
    cudaGetSymbolAddress((void**)&w1h,  g_w1);
    cudaGetSymbolAddress((void**)&w2h,  g_w2);

    cudaFuncSetAttribute(gemm_f16, cudaFuncAttributeMaxDynamicSharedMemorySize,
                         GSMEM_BYTES);
    cudaFuncSetAttribute(attn_kernel, cudaFuncAttributeMaxDynamicSharedMemorySize,
                         ASMEM_BYTES);

    // LN1 + weight conversion fused into one launch (disjoint block ranges)
    ln_cvt_kernel<<<ROWS + 12 * E_ * E_ / 1024, 256>>>(
        x, ln1_g, ln1_b, xn,
        in_proj_w, out_w, w1, w2, wqkv, wout, w1h, w2h);

    gemm_f16<<<dim3(3 * E_ / 128, ROWS / 128), 128, GSMEM_BYTES>>>(
        xn, wqkv, in_proj_b, nullptr, nullptr, qkv, ROWS, 3 * E_, E_, 0);
    attn_kernel<<<dim3(N_ / 128, H_, B_), 256, ASMEM_BYTES>>>(qkv, rel_pos, o);
    gemm_f16<<<dim3(E_ / 128, ROWS / 128), 128, GSMEM_BYTES>>>(
        o, wout, out_b, x, out, nullptr, ROWS, E_, E_, 0);
    ln_kernel<<<ROWS, 256>>>(out, ln2_g, ln2_b, xm);
    gemm_f16<<<dim3(FF / 128, ROWS / 128), 128, GSMEM_BYTES>>>(
        xm, w1h, b1, nullptr, nullptr, hbuf, ROWS, FF, E_, 1);
    gemm_f16<<<dim3(E_ / 128, ROWS / 128), 128, GSMEM_BYTES>>>(
        hbuf, w2h, b2, out, out, nullptr, ROWS, E_, FF, 0);
}